// round 3
// baseline (speedup 1.0000x reference)
#include <cuda_runtime.h>

#define H 256
#define NMAX 20000
#define EMAX 320000
#define GMAX 1000
#define DIS 384

// ---------------- device scratch (static globals: no allocation APIs) ----------------
__device__ int   g_is64;
__device__ int   g_src[EMAX];
__device__ int   g_dst[EMAX];
__device__ int   g_e2g[EMAX];
__device__ float g_h[NMAX * H];
__device__ float g_P[NMAX * H];
__device__ float g_Q[NMAX * H];
__device__ float g_S[NMAX * H];
__device__ float g_R[GMAX * H];
__device__ float g_femb[(size_t)EMAX * DIS];
__device__ float g_e1[(size_t)EMAX * H];
__device__ float g_sums[NMAX * H];
__device__ float g_cnt[NMAX];
__device__ float g_rcnt[NMAX];
__device__ float g_t1[NMAX * H];

__device__ __forceinline__ float dsilu(float x) {
    return __fdividef(x, 1.0f + __expf(-x));
}

// ---------------- index dtype detection + conversion ----------------
// If edge_index arrived as int64 (values < 2^31, non-negative), every odd 32-bit
// word is zero. For int32 data the odd words are random node ids — all-zero over
// 2048 samples is statistically impossible.
__global__ void detect_k(const void* eidx, int E) {
    __shared__ int any;
    if (threadIdx.x == 0) any = 0;
    __syncthreads();
    const int* w = (const int*)eidx;
    int lim = 2048 < (E - 1) ? 2048 : (E - 1);
    for (int i = threadIdx.x; i < lim; i += blockDim.x) {
        if (w[2 * i + 1] != 0) any = 1;
    }
    __syncthreads();
    if (threadIdx.x == 0) g_is64 = (any == 0) ? 1 : 0;
}

__global__ void convert_k(const void* eidx, const void* e2g, int E) {
    int i = blockIdx.x * blockDim.x + threadIdx.x;
    if (i >= E) return;
    if (g_is64) {
        const long long* p = (const long long*)eidx;
        const long long* q = (const long long*)e2g;
        g_src[i] = (int)p[i];
        g_dst[i] = (int)p[(size_t)E + i];
        g_e2g[i] = (int)q[i];
    } else {
        const int* p = (const int*)eidx;
        const int* q = (const int*)e2g;
        g_src[i] = p[i];
        g_dst[i] = p[E + i];
        g_e2g[i] = q[i];
    }
}

// ---------------- zero accumulators (must run every graph replay) ----------------
__global__ void zero_k(int Nn) {
    int i = blockIdx.x * blockDim.x + threadIdx.x;
    if (i < Nn * H) g_sums[i] = 0.0f;
    if (i < Nn) g_cnt[i] = 0.0f;
}

// ---------------- layernorm: one block per row ----------------
__global__ __launch_bounds__(256) void ln_k(const float* __restrict__ x,
                                            const float* __restrict__ gm,
                                            const float* __restrict__ bt) {
    int row = blockIdx.x;
    int c = threadIdx.x;
    float v = x[(size_t)row * H + c];
    float s = v, ss = v * v;
#pragma unroll
    for (int o = 16; o; o >>= 1) {
        s  += __shfl_xor_sync(0xffffffffu, s, o);
        ss += __shfl_xor_sync(0xffffffffu, ss, o);
    }
    __shared__ float as[8], bs[8];
    if ((c & 31) == 0) { as[c >> 5] = s; bs[c >> 5] = ss; }
    __syncthreads();
    s = 0.f; ss = 0.f;
#pragma unroll
    for (int i = 0; i < 8; i++) { s += as[i]; ss += bs[i]; }
    float mu  = s * (1.0f / H);
    float var = ss * (1.0f / H) - mu * mu;
    float inv = rsqrtf(var + 1e-5f);
    g_h[(size_t)row * H + c] = (v - mu) * inv * gm[c] + bt[c];
}

// ---------------- R[g] = (L@L^T).flatten() @ We1[512:521] + be1 ----------------
__global__ __launch_bounds__(256) void lat_k(const float* __restrict__ L,
                                             const float* __restrict__ We1,
                                             const float* __restrict__ be1) {
    int g = blockIdx.x;
    __shared__ float ll[9];
    if (threadIdx.x < 9) {
        int i = threadIdx.x / 3, k = threadIdx.x % 3;
        const float* Lg = L + g * 9;
        ll[threadIdx.x] = Lg[i * 3 + 0] * Lg[k * 3 + 0] +
                          Lg[i * 3 + 1] * Lg[k * 3 + 1] +
                          Lg[i * 3 + 2] * Lg[k * 3 + 2];
    }
    __syncthreads();
    int c = threadIdx.x;
    float a = be1[c];
#pragma unroll
    for (int p = 0; p < 9; p++) a += ll[p] * We1[(512 + p) * H + c];
    g_R[g * H + c] = a;
}

// ---------------- sinusoid embedding via angle-addition recurrence ----------------
// 32 edges per block. Fill uses per-lane frequency stagger (f0 = e) so smem
// writes are bank-conflict-free; copy-out is fully coalesced float4.
__global__ __launch_bounds__(256) void femb_k(const float* __restrict__ fd, int E) {
    __shared__ float fs[32 * DIS];  // 49152 B
    const int tid = threadIdx.x;
    const int be = blockIdx.x * 32;
    if (tid < 96) {
        const int e = tid & 31;
        const int d = tid >> 5;
        const int ge = be + e;
        float x = (ge < E) ? fd[ge * 3 + d] : 0.0f;
        float th = 6.28318530717958647692f * x;
        float s1, c1;
        sincosf(th, &s1, &c1);
        int f = e;  // stagger start
        float sf, cf;
        sincosf(th * (float)f, &sf, &cf);
        float* rowS = fs + e * DIS + d * 64;
        float* rowC = rowS + 192;
        for (int i = 0; i < 64; ++i) {
            rowS[f] = sf;
            rowC[f] = cf;
            f++;
            float ns = sf * c1 + cf * s1;
            float nc = cf * c1 - sf * s1;
            bool wrap = (f == 64);
            sf = wrap ? 0.0f : ns;
            cf = wrap ? 1.0f : nc;
            f  = wrap ? 0 : f;
        }
    }
    __syncthreads();
    float4* dst4 = (float4*)(g_femb + (size_t)be * DIS);
    const float4* s4 = (const float4*)fs;
    if (be + 32 <= E) {
        for (int i = tid; i < 32 * 96; i += 256) dst4[i] = s4[i];
    } else {
        for (int i = tid; i < 32 * 96; i += 256)
            if (be + i / 96 < E) dst4[i] = s4[i];
    }
}

// ---------------- edge-degree count + reciprocal ----------------
__global__ void cnt_k(int E) {
    int i = blockIdx.x * blockDim.x + threadIdx.x;
    if (i < E) atomicAdd(&g_cnt[g_src[i]], 1.0f);
}
__global__ void rcnt_k(int Nn) {
    int i = blockIdx.x * blockDim.x + threadIdx.x;
    if (i < Nn) g_rcnt[i] = 1.0f / fmaxf(g_cnt[i], 1.0f);
}

// ---------------- generic 64x64x16 fp32 GEMM with fused epilogues ----------------
// MODE 0: C = A@W                                   (P, Q, S precompute)
// MODE 1: C = silu(A@W + P[src] + Q[dst] + R[e2g])  (edge layer 1; be1 in R)
// MODE 2: atomicAdd(sums[src], silu(A@W + bias))    (edge layer 2 + scatter)
// MODE 3: C = silu((rowScale*A)@W + addRow + bias)  (node layer 1; addRow=S)
// MODE 4: C = addRow + silu(A@W + bias)             (node layer 2 + residual)
template <int MODE>
__global__ __launch_bounds__(256) void gemm_k(
    const float* __restrict__ A, const float* __restrict__ W,
    float* __restrict__ C, int M, int K,
    const int* __restrict__ src, const int* __restrict__ dst,
    const int* __restrict__ e2g,
    const float* __restrict__ Pm, const float* __restrict__ Qm,
    const float* __restrict__ Rm,
    const float* __restrict__ bias,
    const float* __restrict__ rowScale,
    const float* __restrict__ addRow) {
    __shared__ float As[16][68];  // padded: 272 B rows keep float4 alignment, stagger banks
    __shared__ float Bs[16][64];

    const int tid = threadIdx.x;
    const int tx = tid & 15;
    const int ty = tid >> 4;
    const int gm = blockIdx.y * 64;
    const int gn = blockIdx.x * 64;

    const int ar = tid >> 2;         // 0..63
    const int ac = (tid & 3) << 2;   // 0,4,8,12
    const int arow = gm + ar;
    const int br = tid >> 4;         // 0..15
    const int bc = (tid & 15) << 2;  // 0..60

    float rs = 1.0f;
    if (MODE == 3) rs = (arow < M) ? rowScale[arow] : 0.0f;

    float acc[4][4];
#pragma unroll
    for (int i = 0; i < 4; i++)
#pragma unroll
        for (int j = 0; j < 4; j++) acc[i][j] = 0.0f;

    const float* Ap = A + (size_t)arow * K + ac;
    const float* Wp = W + (size_t)br * H + gn + bc;

    for (int k0 = 0; k0 < K; k0 += 16) {
        float4 av = make_float4(0.f, 0.f, 0.f, 0.f);
        if (arow < M) av = *(const float4*)(Ap + k0);
        if (MODE == 3) { av.x *= rs; av.y *= rs; av.z *= rs; av.w *= rs; }
        float4 bv = *(const float4*)(Wp + (size_t)k0 * H);
        __syncthreads();
        As[ac + 0][ar] = av.x;
        As[ac + 1][ar] = av.y;
        As[ac + 2][ar] = av.z;
        As[ac + 3][ar] = av.w;
        *(float4*)&Bs[br][bc] = bv;
        __syncthreads();
#pragma unroll
        for (int kk = 0; kk < 16; ++kk) {
            float4 a = *(const float4*)&As[kk][ty << 2];
            float4 b = *(const float4*)&Bs[kk][tx << 2];
            acc[0][0] += a.x * b.x; acc[0][1] += a.x * b.y; acc[0][2] += a.x * b.z; acc[0][3] += a.x * b.w;
            acc[1][0] += a.y * b.x; acc[1][1] += a.y * b.y; acc[1][2] += a.y * b.z; acc[1][3] += a.y * b.w;
            acc[2][0] += a.z * b.x; acc[2][1] += a.z * b.y; acc[2][2] += a.z * b.z; acc[2][3] += a.z * b.w;
            acc[3][0] += a.w * b.x; acc[3][1] += a.w * b.y; acc[3][2] += a.w * b.z; acc[3][3] += a.w * b.w;
        }
    }

    const int col = gn + (tx << 2);
#pragma unroll
    for (int i = 0; i < 4; i++) {
        const int row = gm + (ty << 2) + i;
        if (row >= M) continue;
        float v0 = acc[i][0], v1 = acc[i][1], v2 = acc[i][2], v3 = acc[i][3];
        if (MODE == 0) {
            *(float4*)&C[(size_t)row * H + col] = make_float4(v0, v1, v2, v3);
        } else if (MODE == 1) {
            int s = src[row], d = dst[row], g = e2g[row];
            float4 p = *(const float4*)&Pm[(size_t)s * H + col];
            float4 q = *(const float4*)&Qm[(size_t)d * H + col];
            float4 r = *(const float4*)&Rm[(size_t)g * H + col];
            float4 o;
            o.x = dsilu(v0 + p.x + q.x + r.x);
            o.y = dsilu(v1 + p.y + q.y + r.y);
            o.z = dsilu(v2 + p.z + q.z + r.z);
            o.w = dsilu(v3 + p.w + q.w + r.w);
            *(float4*)&C[(size_t)row * H + col] = o;
        } else if (MODE == 2) {
            int s = src[row];
            float4 bb = *(const float4*)&bias[col];
            atomicAdd(&C[(size_t)s * H + col + 0], dsilu(v0 + bb.x));
            atomicAdd(&C[(size_t)s * H + col + 1], dsilu(v1 + bb.y));
            atomicAdd(&C[(size_t)s * H + col + 2], dsilu(v2 + bb.z));
            atomicAdd(&C[(size_t)s * H + col + 3], dsilu(v3 + bb.w));
        } else if (MODE == 3) {
            float4 bb = *(const float4*)&bias[col];
            float4 ad = *(const float4*)&addRow[(size_t)row * H + col];
            float4 o;
            o.x = dsilu(v0 + ad.x + bb.x);
            o.y = dsilu(v1 + ad.y + bb.y);
            o.z = dsilu(v2 + ad.z + bb.z);
            o.w = dsilu(v3 + ad.w + bb.w);
            *(float4*)&C[(size_t)row * H + col] = o;
        } else {  // MODE 4
            float4 bb = *(const float4*)&bias[col];
            float4 ad = *(const float4*)&addRow[(size_t)row * H + col];
            float4 o;
            o.x = ad.x + dsilu(v0 + bb.x);
            o.y = ad.y + dsilu(v1 + bb.y);
            o.z = ad.z + dsilu(v2 + bb.z);
            o.w = ad.w + dsilu(v3 + bb.w);
            *(float4*)&C[(size_t)row * H + col] = o;
        }
    }
}

// ---------------- host side ----------------
static float *p_h = nullptr, *p_P = nullptr, *p_Q = nullptr, *p_S = nullptr,
             *p_R = nullptr, *p_femb = nullptr, *p_e1 = nullptr,
             *p_sums = nullptr, *p_t1 = nullptr, *p_rcnt = nullptr;
static int *p_src = nullptr, *p_dst = nullptr, *p_e2g = nullptr;

static void init_ptrs() {
    if (p_h) return;
    cudaGetSymbolAddress((void**)&p_h, g_h);
    cudaGetSymbolAddress((void**)&p_P, g_P);
    cudaGetSymbolAddress((void**)&p_Q, g_Q);
    cudaGetSymbolAddress((void**)&p_S, g_S);
    cudaGetSymbolAddress((void**)&p_R, g_R);
    cudaGetSymbolAddress((void**)&p_femb, g_femb);
    cudaGetSymbolAddress((void**)&p_e1, g_e1);
    cudaGetSymbolAddress((void**)&p_sums, g_sums);
    cudaGetSymbolAddress((void**)&p_t1, g_t1);
    cudaGetSymbolAddress((void**)&p_rcnt, g_rcnt);
    cudaGetSymbolAddress((void**)&p_src, g_src);
    cudaGetSymbolAddress((void**)&p_dst, g_dst);
    cudaGetSymbolAddress((void**)&p_e2g, g_e2g);
}
namespace {
struct Boot {  // force module load (device globals materialize) before harness checkpoints
    Boot() { init_ptrs(); }
};
static Boot boot_;
}  // namespace

extern "C" void kernel_launch(void* const* d_in, const int* in_sizes, int n_in,
                              void* d_out, int out_size) {
    init_ptrs();
    const float* nf  = (const float*)d_in[0];
    const float* lat = (const float*)d_in[1];
    const void*  eix = d_in[2];
    const void*  e2g = d_in[3];
    const float* fd  = (const float*)d_in[4];
    // d_in[5] = num_atoms (unused by reference)
    const float* gam = (const float*)d_in[6];
    const float* bet = (const float*)d_in[7];
    const float* We1 = (const float*)d_in[8];
    const float* be1 = (const float*)d_in[9];
    const float* We2 = (const float*)d_in[10];
    const float* be2 = (const float*)d_in[11];
    const float* Wn1 = (const float*)d_in[12];
    const float* bn1 = (const float*)d_in[13];
    const float* Wn2 = (const float*)d_in[14];
    const float* bn2 = (const float*)d_in[15];
    float* out = (float*)d_out;

    const int Nn = in_sizes[0] / H;
    const int Gn = in_sizes[1] / 9;
    const int E  = in_sizes[4] / 3;

    detect_k<<<1, 256>>>(eix, E);
    convert_k<<<(E + 255) / 256, 256>>>(eix, e2g, E);
    zero_k<<<(Nn * H + 255) / 256, 256>>>(Nn);
    ln_k<<<Nn, 256>>>(nf, gam, bet);
    lat_k<<<Gn, 256>>>(lat, We1, be1);

    dim3 gN(4, (Nn + 63) / 64);
    dim3 gE(4, (E + 63) / 64);

    // node-side precomputes: P = h@We1[:H], Q = h@We1[H:2H], S = h@Wn1[:H]
    gemm_k<0><<<gN, 256>>>(p_h, We1, p_P, Nn, H, 0, 0, 0, 0, 0, 0, 0, 0, 0);
    gemm_k<0><<<gN, 256>>>(p_h, We1 + 256 * H, p_Q, Nn, H, 0, 0, 0, 0, 0, 0, 0, 0, 0);
    gemm_k<0><<<gN, 256>>>(p_h, Wn1, p_S, Nn, H, 0, 0, 0, 0, 0, 0, 0, 0, 0);

    femb_k<<<(E + 31) / 32, 256>>>(fd, E);

    // edge layer 1: e1 = silu(femb@Wf + P[src] + Q[dst] + R[e2g])
    gemm_k<1><<<gE, 256>>>(p_femb, We1 + 521 * H, p_e1, E, DIS,
                           p_src, p_dst, p_e2g, p_P, p_Q, p_R, 0, 0, 0);

    cnt_k<<<(E + 255) / 256, 256>>>(E);

    // edge layer 2 + scatter-add into sums
    gemm_k<2><<<gE, 256>>>(p_e1, We2, p_sums, E, H,
                           p_src, 0, 0, 0, 0, 0, be2, 0, 0);

    rcnt_k<<<(Nn + 255) / 256, 256>>>(Nn);

    // node layer 1: t1 = silu(agg@Wn1[H:] + S + bn1), agg = sums * rcnt
    gemm_k<3><<<gN, 256>>>(p_sums, Wn1 + 256 * H, p_t1, Nn, H,
                           0, 0, 0, 0, 0, 0, bn1, p_rcnt, p_S);

    // node layer 2 + residual
    gemm_k<4><<<gN, 256>>>(p_t1, Wn2, out, Nn, H,
                           0, 0, 0, 0, 0, 0, bn2, 0, nf);
}